// round 5
// baseline (speedup 1.0000x reference)
#include <cuda_runtime.h>

// Shapes fixed by the reference
#define BB 16
#define TT 8192
#define CC 512
#define YY 256
#define C4 (CC / 4)            // 128 float4 lanes per frame row
#define NSPAN (BB * YY)        // 4096
#define GRID_POOL (148 * 16)   // persistent blocks, 16/SM -> 2048 threads/SM

// Work-stealing state (module-static, self-restoring each launch)
__device__ int g_next = GRID_POOL;
__device__ int g_done = 0;

// ---------------------------------------------------------------------------
// Fused persistent kernel (one launch).
// Each block steals whole spans (b, y). Per span:
//   0. thread 0 prefetches the NEXT span id (atomic latency hidden under loop)
//   1. threads 0..63 reduce durations[b, 0..y-1] -> start; pick dur[b,y] -> cnt
//   2. 128 threads mean-pool: one float4 channel lane each -> fully
//      contiguous 2048B per frame row, unroll x4 (known-good 76%+ pattern).
// Last block restores the steal counters (graph-replay safe, deterministic).
// ---------------------------------------------------------------------------
__global__ void __launch_bounds__(128, 16)
pool_fused_kernel(const float* __restrict__ emg,
                  const int*   __restrict__ dur,
                  float*       __restrict__ out) {
    __shared__ int sh[4];            // [0],[1] warp sums, [2] cnt, [3] next id
    const int tid = threadIdx.x;     // 0..127

    int by = blockIdx.x;
    while (by < NSPAN) {
        // ---- prefetch next span id (consumed at bottom of this iteration) --
        if (tid == 0) sh[3] = atomicAdd(&g_next, 1);

        const int b = by >> 8;       // YY == 256
        const int y = by & 255;

        // ---- span metadata: start = sum_{j<y} dur[b,j], cnt = dur[b,y] ----
        if (tid < 64) {
            const int4 v = __ldg(reinterpret_cast<const int4*>(dur) + b * 64 + tid);
            const int base = tid * 4;
            int s = 0;
            if (base + 0 < y) s += v.x;
            if (base + 1 < y) s += v.y;
            if (base + 2 < y) s += v.z;
            if (base + 3 < y) s += v.w;
            if ((y >> 2) == tid) {
                int c;
                switch (y & 3) {
                    case 0:  c = v.x; break;
                    case 1:  c = v.y; break;
                    case 2:  c = v.z; break;
                    default: c = v.w; break;
                }
                sh[2] = c;
            }
            #pragma unroll
            for (int o = 16; o; o >>= 1) s += __shfl_down_sync(0xffffffffu, s, o);
            if ((tid & 31) == 0) sh[tid >> 5] = s;
        }
        __syncthreads();

        const int start_raw = sh[0] + sh[1];
        const int st  = min(start_raw, TT);
        const int en  = min(start_raw + sh[2], TT);
        const int cnt = en - st;

        // ---- mean-pool cnt frames (unroll x4, plain loads) ----
        const float4* p = reinterpret_cast<const float4*>(emg)
                          + ((size_t)b * TT + st) * C4 + tid;

        float4 a0 = make_float4(0.f, 0.f, 0.f, 0.f);
        float4 a1 = a0, a2 = a0, a3 = a0;

        int t = 0;
        for (; t + 4 <= cnt; t += 4) {
            const float4 v0 = p[0 * C4];
            const float4 v1 = p[1 * C4];
            const float4 v2 = p[2 * C4];
            const float4 v3 = p[3 * C4];
            a0.x += v0.x; a0.y += v0.y; a0.z += v0.z; a0.w += v0.w;
            a1.x += v1.x; a1.y += v1.y; a1.z += v1.z; a1.w += v1.w;
            a2.x += v2.x; a2.y += v2.y; a2.z += v2.z; a2.w += v2.w;
            a3.x += v3.x; a3.y += v3.y; a3.z += v3.z; a3.w += v3.w;
            p += 4 * C4;
        }
        for (; t < cnt; t++) {
            const float4 vv = p[0];
            a0.x += vv.x; a0.y += vv.y; a0.z += vv.z; a0.w += vv.w;
            p += C4;
        }

        const float inv = (cnt > 0) ? (1.0f / (float)cnt) : 0.0f;
        float4 r;
        r.x = ((a0.x + a1.x) + (a2.x + a3.x)) * inv;
        r.y = ((a0.y + a1.y) + (a2.y + a3.y)) * inv;
        r.z = ((a0.z + a1.z) + (a2.z + a3.z)) * inv;
        r.w = ((a0.w + a1.w) + (a2.w + a3.w)) * inv;

        reinterpret_cast<float4*>(out)[(size_t)by * C4 + tid] = r;

        // ---- consume prefetched span id ----
        __syncthreads();             // all reads of sh done; sh[3] visible
        by = sh[3];
        __syncthreads();             // protect sh[*] rewrite next iteration
    }

    // ---- last block restores steal state for the next (graph) launch ----
    if (tid == 0) {
        const int d = atomicAdd(&g_done, 1);
        if (d == GRID_POOL - 1) {
            g_next = GRID_POOL;
            g_done = 0;
            __threadfence();
        }
    }
}

extern "C" void kernel_launch(void* const* d_in, const int* in_sizes, int n_in,
                              void* d_out, int out_size) {
    const float* emg = (const float*)d_in[0];
    const int*   dur = (const int*)d_in[1];
    float*       out = (float*)d_out;

    pool_fused_kernel<<<GRID_POOL, 128>>>(emg, dur, out);
}

// round 6
// speedup vs baseline: 1.1181x; 1.1181x over previous
#include <cuda_runtime.h>

// Shapes fixed by the reference
#define BB 16
#define TT 8192
#define CC 512
#define YY 256
#define C4 (CC / 4)            // 128 float4 lanes per frame row
#define NSPAN (BB * YY)        // 4096
#define BLKS_PER_SM 10
#define GRID_POOL (148 * BLKS_PER_SM)

// Work-stealing state (module-static, self-restoring each launch)
__device__ int g_next = GRID_POOL;
__device__ int g_done = 0;

// ---------------------------------------------------------------------------
// Fused persistent kernel (one launch).
// Each block steals whole spans (b, y). Per span:
//   0. thread 0 prefetches the NEXT span id (atomic hidden under frame loop)
//   1. threads 0..63 reduce durations[b, 0..y-1] -> start; pick dur[b,y] -> cnt
//   2. 128 threads mean-pool: one float4 channel lane each -> fully
//      contiguous 2048B per frame row. Unroll x4 with only TWO accumulators:
//      the 4 loads remain independent (full MLP) while register pressure
//      stays within the 51-reg budget for 10 blocks/SM (64K regs / SM).
// Last block restores the steal counters (graph-replay safe, deterministic).
// ---------------------------------------------------------------------------
__global__ void __launch_bounds__(128, BLKS_PER_SM)
pool_fused_kernel(const float* __restrict__ emg,
                  const int*   __restrict__ dur,
                  float*       __restrict__ out) {
    __shared__ int sh[4];            // [0],[1] warp sums, [2] cnt, [3] next id
    const int tid = threadIdx.x;     // 0..127

    int by = blockIdx.x;
    while (by < NSPAN) {
        // ---- prefetch next span id ----
        if (tid == 0) sh[3] = atomicAdd(&g_next, 1);

        const int b = by >> 8;       // YY == 256
        const int y = by & 255;

        // ---- span metadata: start = sum_{j<y} dur[b,j], cnt = dur[b,y] ----
        if (tid < 64) {
            const int4 v = __ldg(reinterpret_cast<const int4*>(dur) + b * 64 + tid);
            const int base = tid * 4;
            int s = 0;
            if (base + 0 < y) s += v.x;
            if (base + 1 < y) s += v.y;
            if (base + 2 < y) s += v.z;
            if (base + 3 < y) s += v.w;
            if ((y >> 2) == tid) {
                int c;
                switch (y & 3) {
                    case 0:  c = v.x; break;
                    case 1:  c = v.y; break;
                    case 2:  c = v.z; break;
                    default: c = v.w; break;
                }
                sh[2] = c;
            }
            #pragma unroll
            for (int o = 16; o; o >>= 1) s += __shfl_down_sync(0xffffffffu, s, o);
            if ((tid & 31) == 0) sh[tid >> 5] = s;
        }
        __syncthreads();

        const int start_raw = sh[0] + sh[1];
        const int st  = min(start_raw, TT);
        const int en  = min(start_raw + sh[2], TT);
        const int cnt = en - st;

        // ---- mean-pool cnt frames (unroll x4 loads, 2 accumulators) ----
        const float4* p = reinterpret_cast<const float4*>(emg)
                          + ((size_t)b * TT + st) * C4 + tid;

        float4 a0 = make_float4(0.f, 0.f, 0.f, 0.f);
        float4 a1 = a0;

        int t = 0;
        for (; t + 4 <= cnt; t += 4) {
            const float4 v0 = p[0 * C4];
            const float4 v1 = p[1 * C4];
            const float4 v2 = p[2 * C4];
            const float4 v3 = p[3 * C4];
            a0.x += v0.x; a0.y += v0.y; a0.z += v0.z; a0.w += v0.w;
            a1.x += v2.x; a1.y += v2.y; a1.z += v2.z; a1.w += v2.w;
            a0.x += v1.x; a0.y += v1.y; a0.z += v1.z; a0.w += v1.w;
            a1.x += v3.x; a1.y += v3.y; a1.z += v3.z; a1.w += v3.w;
            p += 4 * C4;
        }
        for (; t < cnt; t++) {
            const float4 vv = p[0];
            a0.x += vv.x; a0.y += vv.y; a0.z += vv.z; a0.w += vv.w;
            p += C4;
        }

        const float inv = (cnt > 0) ? (1.0f / (float)cnt) : 0.0f;
        float4 r;
        r.x = (a0.x + a1.x) * inv;
        r.y = (a0.y + a1.y) * inv;
        r.z = (a0.z + a1.z) * inv;
        r.w = (a0.w + a1.w) * inv;

        reinterpret_cast<float4*>(out)[(size_t)by * C4 + tid] = r;

        // ---- consume prefetched span id ----
        __syncthreads();
        by = sh[3];
        __syncthreads();
    }

    // ---- last block restores steal state for the next (graph) launch ----
    if (tid == 0) {
        const int d = atomicAdd(&g_done, 1);
        if (d == GRID_POOL - 1) {
            g_next = GRID_POOL;
            g_done = 0;
            __threadfence();
        }
    }
}

extern "C" void kernel_launch(void* const* d_in, const int* in_sizes, int n_in,
                              void* d_out, int out_size) {
    const float* emg = (const float*)d_in[0];
    const int*   dur = (const int*)d_in[1];
    float*       out = (float*)d_out;

    pool_fused_kernel<<<GRID_POOL, 128>>>(emg, dur, out);
}